// round 9
// baseline (speedup 1.0000x reference)
#include <cuda_runtime.h>
#include <cuda_fp16.h>
#include <mma.h>
#include <cstdint>

using namespace nvcuda;

#define NNODES 100000
#define NEDGES 1600000
#define NSCANBLK 98        // ceil(NNODES/1024)

// ---------------- device scratch ----------------
__device__ int    g_deg_out[NNODES];
__device__ int    g_deg_in[NNODES];
__device__ float  g_o[NNODES];
__device__ float  g_i[NNODES];
__device__ float  g_schain[NNODES];     // i~[r]*o[r]
__device__ float2 g_gs[NNODES];         // {1/i~[r], o~[r]/i~[r]}
__device__ int    g_rowptrA[NNODES + 1];
__device__ int    g_rowptrAT[NNODES + 1];
__device__ int    g_curA[NNODES];
__device__ int    g_curAT[NNODES];
__device__ int    g_colA[NEDGES];
__device__ int    g_colAT[NEDGES];
__device__ unsigned long long g_tstat[2][NSCANBLK];
__device__ int    g_hopbar[4];          // persistent-kernel barrier counters
__device__ __half g_xh [(size_t)NNODES * 64];
__device__ __half g_y1h[(size_t)NNODES * 64];
__device__ __half g_y2h[(size_t)NNODES * 64];
__device__ __half g_y3h[(size_t)NNODES * 64];
__device__ __half g_y4h[(size_t)NNODES * 64];
__device__ __half g_Zh [(size_t)NNODES * 64];
__device__ float  g_bias[64];
__device__ __half g_Uh[128 * 320];

// ---------------- init: zero degs/status/barriers + build U/bias ----------------
__global__ void init_kernel(const float* __restrict__ Wsd, const float* __restrict__ Wds,
                            const float* __restrict__ W0sd, const float* __restrict__ W0ds,
                            const float* __restrict__ bssd, const float* __restrict__ bsds,
                            const float* __restrict__ b0sd, const float* __restrict__ b0ds) {
    int t = blockIdx.x * blockDim.x + threadIdx.x;
    if (t < NNODES) { g_deg_out[t] = 0; g_deg_in[t] = 0; }
    if (t < 2 * NSCANBLK) g_tstat[t >= NSCANBLK][t % NSCANBLK] = 0ull;
    if (t < 4) g_hopbar[t] = 0;

    if (t < 128 * 320) {
        int c = t / 320;
        int kk = t - c * 320;
        int b = kk >> 6;
        int k = kk & 63;
        float v;
        float coef = exp2f(-(float)b);
        if (c < 64) {
            if (b == 0) v = 0.5f * (W0sd[c * 64 + k] + W0ds[c * 64 + k]);
            else        v = coef * Wsd[(b - 1) * 4096 + c * 64 + k];
        } else {
            int cc = c - 64;
            if (b == 0)      v = 0.5f * Wds[cc * 64 + k];
            else if (b == 1) v = 0.0f;
            else             v = coef * Wds[(b - 1) * 4096 + cc * 64 + k];
        }
        g_Uh[t] = __float2half(v);
    }
    if (t < 64) {
        float bsum = b0sd[t] + b0ds[t];
        float sc = 1.0f;
        #pragma unroll
        for (int kk = 0; kk < 4; kk++) {
            bsum += sc * (bssd[kk * 64 + t] + bsds[kk * 64 + t]);
            sc *= 0.5f;
        }
        g_bias[t] = 0.5f * bsum;
    }
}

__global__ void count_deg_kernel(const int* __restrict__ ei) {
    int t = blockIdx.x * blockDim.x + threadIdx.x;
    if (t < NEDGES / 4) {
        int4 r = __ldg((const int4*)ei + t);
        int4 c = __ldg((const int4*)(ei + NEDGES) + t);
        atomicAdd(&g_deg_out[r.x], 1);
        atomicAdd(&g_deg_out[r.y], 1);
        atomicAdd(&g_deg_out[r.z], 1);
        atomicAdd(&g_deg_out[r.w], 1);
        atomicAdd(&g_deg_in[c.x], 1);
        atomicAdd(&g_deg_in[c.y], 1);
        atomicAdd(&g_deg_in[c.z], 1);
        atomicAdd(&g_deg_in[c.w], 1);
    }
}

// ---------------- single-pass exclusive scan (decoupled lookback) ----------------
__global__ void scan_lookback_kernel() {
    __shared__ int s[1024];
    __shared__ int s_prefix;
    const int sel = blockIdx.y;
    const int* deg = sel ? g_deg_in : g_deg_out;
    unsigned long long* tstat = g_tstat[sel];
    int* rowptr = sel ? g_rowptrAT : g_rowptrA;
    int* cursor = sel ? g_curAT : g_curA;
    float* nrm  = sel ? g_i : g_o;

    const int tid = threadIdx.x;
    const int i = blockIdx.x * 1024 + tid;
    int v = (i < NNODES) ? deg[i] : 0;
    s[tid] = v;
    __syncthreads();
    #pragma unroll
    for (int off = 1; off < 1024; off <<= 1) {
        int t = (tid >= off) ? s[tid - off] : 0;
        __syncthreads();
        s[tid] += t;
        __syncthreads();
    }
    int incl = s[tid];
    int aggregate = s[1023];

    if (tid == 0) {
        if (blockIdx.x == 0) {
            atomicExch(&tstat[0], (2ull << 32) | (unsigned)aggregate);
            s_prefix = 0;
        } else {
            atomicExch(&tstat[blockIdx.x], (1ull << 32) | (unsigned)aggregate);
            int pfx = 0;
            int j = blockIdx.x - 1;
            for (;;) {
                unsigned long long st;
                do { st = atomicAdd(&tstat[j], 0ull); } while ((st >> 32) == 0ull);
                pfx += (int)(unsigned)st;
                if ((st >> 32) == 2ull) break;
                j--;
            }
            atomicExch(&tstat[blockIdx.x], (2ull << 32) | (unsigned)(aggregate + pfx));
            s_prefix = pfx;
        }
    }
    __syncthreads();

    if (i < NNODES) {
        int excl = s_prefix + incl - v;
        rowptr[i] = excl;
        cursor[i] = excl;
        nrm[i] = (v > 0) ? rsqrtf((float)v) : 0.0f;
    }
    if (i == 0) rowptr[NNODES] = NEDGES;
}

// ---------------- merged combine + fill_csr (both depend only on scan) ----------------
__global__ void combfill_kernel(const float* __restrict__ x, const int* __restrict__ ei) {
    int t = blockIdx.x * blockDim.x + threadIdx.x;

    // fill CSR: 4 edges/thread, independent atomic chains
    if (t < NEDGES / 4) {
        int4 r = __ldg((const int4*)ei + t);
        int4 c = __ldg((const int4*)(ei + NEDGES) + t);
        int p0 = atomicAdd(&g_curA[r.x], 1);
        int p1 = atomicAdd(&g_curA[r.y], 1);
        int p2 = atomicAdd(&g_curA[r.z], 1);
        int p3 = atomicAdd(&g_curA[r.w], 1);
        int q0 = atomicAdd(&g_curAT[c.x], 1);
        int q1 = atomicAdd(&g_curAT[c.y], 1);
        int q2 = atomicAdd(&g_curAT[c.z], 1);
        int q3 = atomicAdd(&g_curAT[c.w], 1);
        g_colA[p0] = c.x;
        g_colA[p1] = c.y;
        g_colA[p2] = c.z;
        g_colA[p3] = c.w;
        g_colAT[q0] = r.x;
        g_colAT[q1] = r.y;
        g_colAT[q2] = r.z;
        g_colAT[q3] = r.w;
    }

    // combine: x -> i~*x (fp16) + derived row scales
    if (t < NNODES * 16) {
        int r = t >> 4;
        float ii = g_i[r];
        float it = (ii > 0.f) ? ii : 1.0f;
        float4 v = __ldg((const float4*)x + t);
        __half2 h0 = __floats2half2_rn(it * v.x, it * v.y);
        __half2 h1 = __floats2half2_rn(it * v.z, it * v.w);
        uint2 o;
        o.x = *reinterpret_cast<unsigned*>(&h0);
        o.y = *reinterpret_cast<unsigned*>(&h1);
        *((uint2*)g_xh + t) = o;
    }
    if (t < NNODES) {
        float ii = g_i[t];
        float oo = g_o[t];
        float it = (ii > 0.f) ? ii : 1.0f;
        float ot = (oo > 0.f) ? oo : 1.0f;
        g_schain[t] = it * oo;
        g_gs[t] = make_float2(1.0f / it, ot / it);
    }
}

// ---------------- SpMM row body (R5/R8 proven unroll-2 gather) ----------------
__device__ __forceinline__ void spmm_row_accum(const int* __restrict__ cidx,
                                               const __half* __restrict__ hl,
                                               int k, int end, float* a) {
    float b[8] = {0.f, 0.f, 0.f, 0.f, 0.f, 0.f, 0.f, 0.f};
    while (k + 2 <= end) {
        int c0 = __ldg(cidx + k);
        int c1 = __ldg(cidx + k + 1);
        uint4 h0 = __ldg((const uint4*)(hl + ((size_t)c0 << 6)));
        uint4 h1 = __ldg((const uint4*)(hl + ((size_t)c1 << 6)));
        const unsigned* p0 = &h0.x;
        const unsigned* p1 = &h1.x;
        #pragma unroll
        for (int q = 0; q < 4; q++) {
            float2 f0 = __half22float2(*reinterpret_cast<const __half2*>(p0 + q));
            float2 f1 = __half22float2(*reinterpret_cast<const __half2*>(p1 + q));
            a[q * 2]     += f0.x;
            a[q * 2 + 1] += f0.y;
            b[q * 2]     += f1.x;
            b[q * 2 + 1] += f1.y;
        }
        k += 2;
    }
    if (k < end) {
        int c0 = __ldg(cidx + k);
        uint4 h0 = __ldg((const uint4*)(hl + ((size_t)c0 << 6)));
        const unsigned* p0 = &h0.x;
        #pragma unroll
        for (int q = 0; q < 4; q++) {
            float2 f0 = __half22float2(*reinterpret_cast<const __half2*>(p0 + q));
            a[q * 2]     += f0.x;
            a[q * 2 + 1] += f0.y;
        }
    }
    #pragma unroll
    for (int q = 0; q < 8; q++) a[q] += b[q];
}

// ---------------- persistent 4-hop chain SpMM with device-wide barrier ----------------
__global__ __launch_bounds__(256) void spmm_chain_kernel() {
    const int nthreads = gridDim.x * blockDim.x;
    const int gt0 = blockIdx.x * blockDim.x + threadIdx.x;

    const __half* bufs[5] = {g_xh, g_y1h, g_y2h, g_y3h, g_y4h};

    #pragma unroll 1
    for (int hop = 0; hop < 4; hop++) {
        const __half* h = bufs[hop];
        __half* yout = (__half*)bufs[hop + 1];

        #pragma unroll 1
        for (int gt = gt0; gt < NNODES * 8; gt += nthreads) {
            int r = gt >> 3;
            int lane = gt & 7;
            int k   = __ldg(g_rowptrA + r);
            int end = __ldg(g_rowptrA + r + 1);
            float a[8] = {0.f, 0.f, 0.f, 0.f, 0.f, 0.f, 0.f, 0.f};
            spmm_row_accum(g_colA, h + (lane << 3), k, end, a);
            float s = g_schain[r];
            uint4 o;
            __half2 h0 = __floats2half2_rn(s * a[0], s * a[1]);
            __half2 h1 = __floats2half2_rn(s * a[2], s * a[3]);
            __half2 h2 = __floats2half2_rn(s * a[4], s * a[5]);
            __half2 h3 = __floats2half2_rn(s * a[6], s * a[7]);
            o.x = *reinterpret_cast<unsigned*>(&h0);
            o.y = *reinterpret_cast<unsigned*>(&h1);
            o.z = *reinterpret_cast<unsigned*>(&h2);
            o.w = *reinterpret_cast<unsigned*>(&h3);
            *(uint4*)(yout + ((size_t)r << 6) + (lane << 3)) = o;
        }

        if (hop < 3) {
            // device-wide barrier: release my writes, arrive, spin, acquire
            __threadfence();
            __syncthreads();
            if (threadIdx.x == 0) {
                atomicAdd(&g_hopbar[hop], 1);
                while (atomicAdd(&g_hopbar[hop], 0) < (int)gridDim.x) {}
            }
            __syncthreads();
            __threadfence();
        }
    }
}

// ---------------- final SpMM: out += bias + i[r] * gather(Zhat) ----------------
__global__ void spmm_final_kernel(float* __restrict__ outf) {
    int gt = blockIdx.x * blockDim.x + threadIdx.x;
    int r = gt >> 3;
    if (r >= NNODES) return;
    int lane = gt & 7;

    int k   = __ldg(g_rowptrAT + r);
    int end = __ldg(g_rowptrAT + r + 1);
    float a[8] = {0.f, 0.f, 0.f, 0.f, 0.f, 0.f, 0.f, 0.f};
    spmm_row_accum(g_colAT, g_Zh + (lane << 3), k, end, a);

    float s = g_i[r];
    size_t off = ((size_t)r << 6) + (lane << 3);
    float4 p0 = *reinterpret_cast<float4*>(outf + off);
    float4 p1 = *reinterpret_cast<float4*>(outf + off + 4);
    float4 bv0 = *reinterpret_cast<const float4*>(g_bias + (lane << 3));
    float4 bv1 = *reinterpret_cast<const float4*>(g_bias + (lane << 3) + 4);
    float4 r0, r1;
    r0.x = p0.x + bv0.x + s * a[0];
    r0.y = p0.y + bv0.y + s * a[1];
    r0.z = p0.z + bv0.z + s * a[2];
    r0.w = p0.w + bv0.w + s * a[3];
    r1.x = p1.x + bv1.x + s * a[4];
    r1.y = p1.y + bv1.y + s * a[5];
    r1.z = p1.z + bv1.z + s * a[6];
    r1.w = p1.w + bv1.w + s * a[7];
    *reinterpret_cast<float4*>(outf + off)     = r0;
    *reinterpret_cast<float4*>(outf + off + 4) = r1;
}

// ---------------- Mega-GEMM via HMMA with per-row epilogue scales ----------------
#define LDS_K 40
__global__ __launch_bounds__(256) void mega_gemm_kernel(
    float* __restrict__ out, __half* __restrict__ Zh)
{
    __shared__ __half sA[128 * LDS_K];
    __shared__ __half sB[128 * LDS_K];
    __shared__ float patch[8][16 * 16];

    const int tid  = threadIdx.x;
    const int wid  = tid >> 5;
    const int row0 = blockIdx.x * 128;
    const int wr   = wid & 3;
    const int wc   = wid >> 2;

    wmma::fragment<wmma::accumulator, 16, 16, 16, float> acc[2][4];
    #pragma unroll
    for (int i = 0; i < 2; i++)
        #pragma unroll
        for (int j = 0; j < 4; j++) wmma::fill_fragment(acc[i][j], 0.0f);

    const __half* srcs[5] = {g_xh, g_y1h, g_y2h, g_y3h, g_y4h};

    const int srow  = tid >> 1;
    const int spart = (tid & 1) * 16;

    #pragma unroll
    for (int g = 0; g < 10; g++) {
        const __half* src = srcs[g >> 1];
        const int kbase = (g & 1) * 32;

        __syncthreads();
        {
            int grow = row0 + srow;
            uint4 v0 = make_uint4(0, 0, 0, 0), v1 = v0;
            if (grow < NNODES) {
                const uint4* p = (const uint4*)(src + (size_t)grow * 64 + kbase + spart);
                v0 = __ldg(p);
                v1 = __ldg(p + 1);
            }
            *(uint4*)&sA[srow * LDS_K + spart]     = v0;
            *(uint4*)&sA[srow * LDS_K + spart + 8] = v1;
        }
        {
            const uint4* p = (const uint4*)(g_Uh + (size_t)srow * 320 + (g >> 1) * 64 + kbase + spart);
            uint4 v0 = __ldg(p);
            uint4 v1 = __ldg(p + 1);
            *(uint4*)&sB[srow * LDS_K + spart]     = v0;
            *(uint4*)&sB[srow * LDS_K + spart + 8] = v1;
        }
        __syncthreads();

        #pragma unroll
        for (int ks = 0; ks < 32; ks += 16) {
            wmma::fragment<wmma::matrix_a, 16, 16, 16, __half, wmma::row_major> af[2];
            wmma::load_matrix_sync(af[0], &sA[(wr * 32 +  0) * LDS_K + ks], LDS_K);
            wmma::load_matrix_sync(af[1], &sA[(wr * 32 + 16) * LDS_K + ks], LDS_K);
            #pragma unroll
            for (int j = 0; j < 4; j++) {
                wmma::fragment<wmma::matrix_b, 16, 16, 16, __half, wmma::col_major> bf;
                wmma::load_matrix_sync(bf, &sB[(wc * 64 + j * 16) * LDS_K + ks], LDS_K);
                wmma::mma_sync(acc[0][j], af[0], bf, acc[0][j]);
                wmma::mma_sync(acc[1][j], af[1], bf, acc[1][j]);
            }
        }
    }

    const int lane = tid & 31;
    #pragma unroll
    for (int i = 0; i < 2; i++) {
        int rbase = row0 + wr * 32 + i * 16;
        if (rbase >= NNODES) continue;
        #pragma unroll
        for (int j = 0; j < 4; j++) {
            wmma::store_matrix_sync(patch[wid], acc[i][j], 16, wmma::mem_row_major);
            __syncwarp();
            int pr = lane >> 1;
            int pc = (lane & 1) * 8;
            int r = rbase + pr;
            const float* pp = &patch[wid][pr * 16 + pc];
            float2 gsr = g_gs[r];
            if (wc == 0) {
                float s = gsr.x;
                float4 o0 = make_float4(pp[0] * s, pp[1] * s, pp[2] * s, pp[3] * s);
                float4 o1 = make_float4(pp[4] * s, pp[5] * s, pp[6] * s, pp[7] * s);
                float* dst = out + (size_t)r * 64 + j * 16 + pc;
                *reinterpret_cast<float4*>(dst)     = o0;
                *reinterpret_cast<float4*>(dst + 4) = o1;
            } else {
                float s = gsr.y;
                __half2 h0 = __floats2half2_rn(pp[0] * s, pp[1] * s);
                __half2 h1 = __floats2half2_rn(pp[2] * s, pp[3] * s);
                __half2 h2 = __floats2half2_rn(pp[4] * s, pp[5] * s);
                __half2 h3 = __floats2half2_rn(pp[6] * s, pp[7] * s);
                uint4 o;
                o.x = *reinterpret_cast<unsigned*>(&h0);
                o.y = *reinterpret_cast<unsigned*>(&h1);
                o.z = *reinterpret_cast<unsigned*>(&h2);
                o.w = *reinterpret_cast<unsigned*>(&h3);
                *(uint4*)(Zh + (size_t)r * 64 + j * 16 + pc) = o;
            }
            __syncwarp();
        }
    }
}

// ---------------- launch ----------------
extern "C" void kernel_launch(void* const* d_in, const int* in_sizes, int n_in,
                              void* d_out, int out_size) {
    const float* x    = (const float*)d_in[0];
    const int*   ei   = (const int*)d_in[1];
    const float* Wsd  = (const float*)d_in[2];
    const float* bssd = (const float*)d_in[3];
    const float* Wds  = (const float*)d_in[4];
    const float* bsds = (const float*)d_in[5];
    const float* W0sd = (const float*)d_in[6];
    const float* b0sd = (const float*)d_in[7];
    const float* W0ds = (const float*)d_in[8];
    const float* b0ds = (const float*)d_in[9];
    float* out = (float*)d_out;

    void* tmp;
    cudaGetSymbolAddress(&tmp, g_Zh);       __half* Zh  = (__half*)tmp;

    const int nblk_nodes = (NNODES + 255) / 256;         // 391
    const int nblk_edge4 = (NEDGES / 4 + 255) / 256;     // 1563
    const int nblk_comb  = (NNODES * 16 + 255) / 256;    // 6250 (covers fill too)
    const int nblk_spmm  = (NNODES * 8 + 255) / 256;     // 3125
    const int nblk_gemm  = (NNODES + 127) / 128;         // 782

    // occupancy-safe persistent grid (all blocks resident -> barrier is deadlock-free)
    int nsm = 148, bpsm = 0;
    cudaDeviceGetAttribute(&nsm, cudaDevAttrMultiProcessorCount, 0);
    cudaOccupancyMaxActiveBlocksPerMultiprocessor(&bpsm, spmm_chain_kernel, 256, 0);
    if (bpsm < 1) bpsm = 1;
    int grid_pers = nsm * bpsm;
    if (grid_pers > nblk_spmm) grid_pers = nblk_spmm;

    // ---- preprocessing (4 launches) ----
    init_kernel<<<nblk_nodes, 256>>>(Wsd, Wds, W0sd, W0ds, bssd, bsds, b0sd, b0ds);
    count_deg_kernel<<<nblk_edge4, 256>>>(ei);
    scan_lookback_kernel<<<dim3(NSCANBLK, 2), 1024>>>();
    combfill_kernel<<<nblk_comb, 256>>>(x, ei);

    // ---- persistent 4-hop chain SpMM (1 launch) ----
    spmm_chain_kernel<<<grid_pers, 256>>>();

    // ---- fused HMMA GEMM ----
    mega_gemm_kernel<<<nblk_gemm, 256>>>(out, Zh);

    // ---- out += bias + i[r] * gather(Zhat) ----
    spmm_final_kernel<<<nblk_spmm, 256>>>(out);
}

// round 10
// speedup vs baseline: 1.1005x; 1.1005x over previous
#include <cuda_runtime.h>
#include <cuda_fp16.h>
#include <mma.h>
#include <cstdint>

using namespace nvcuda;

#define NNODES 100000
#define NEDGES 1600000
#define NSCANBLK 98        // ceil(NNODES/1024)

// ---------------- device scratch ----------------
__device__ int    g_deg_out[NNODES];
__device__ int    g_deg_in[NNODES];
__device__ float  g_o[NNODES];
__device__ float  g_i[NNODES];
__device__ float  g_schain[NNODES];     // i~[r]*o[r]
__device__ float2 g_gs[NNODES];         // {1/i~[r], o~[r]/i~[r]}
__device__ int    g_rowptrA[NNODES + 1];
__device__ int    g_rowptrAT[NNODES + 1];
__device__ int    g_curA[NNODES];
__device__ int    g_curAT[NNODES];
__device__ int    g_colA[NEDGES];
__device__ int    g_colAT[NEDGES];
__device__ unsigned long long g_tstat[2][NSCANBLK];
__device__ __half g_xh [(size_t)NNODES * 64];
__device__ __half g_y1h[(size_t)NNODES * 64];
__device__ __half g_y2h[(size_t)NNODES * 64];
__device__ __half g_y3h[(size_t)NNODES * 64];
__device__ __half g_y4h[(size_t)NNODES * 64];
__device__ __half g_Zh [(size_t)NNODES * 64];
__device__ float  g_bias[64];
__device__ __half g_Uh[128 * 320];

// ---------------- init: zero degs/status + build U/bias ----------------
__global__ void init_kernel(const float* __restrict__ Wsd, const float* __restrict__ Wds,
                            const float* __restrict__ W0sd, const float* __restrict__ W0ds,
                            const float* __restrict__ bssd, const float* __restrict__ bsds,
                            const float* __restrict__ b0sd, const float* __restrict__ b0ds) {
    int t = blockIdx.x * blockDim.x + threadIdx.x;
    if (t < NNODES) { g_deg_out[t] = 0; g_deg_in[t] = 0; }
    if (t < 2 * NSCANBLK) g_tstat[t >= NSCANBLK][t % NSCANBLK] = 0ull;

    if (t < 128 * 320) {
        int c = t / 320;
        int kk = t - c * 320;
        int b = kk >> 6;
        int k = kk & 63;
        float v;
        float coef = exp2f(-(float)b);
        if (c < 64) {
            if (b == 0) v = 0.5f * (W0sd[c * 64 + k] + W0ds[c * 64 + k]);
            else        v = coef * Wsd[(b - 1) * 4096 + c * 64 + k];
        } else {
            int cc = c - 64;
            if (b == 0)      v = 0.5f * Wds[cc * 64 + k];
            else if (b == 1) v = 0.0f;
            else             v = coef * Wds[(b - 1) * 4096 + cc * 64 + k];
        }
        g_Uh[t] = __float2half(v);
    }
    if (t < 64) {
        float bsum = b0sd[t] + b0ds[t];
        float sc = 1.0f;
        #pragma unroll
        for (int kk = 0; kk < 4; kk++) {
            bsum += sc * (bssd[kk * 64 + t] + bsds[kk * 64 + t]);
            sc *= 0.5f;
        }
        g_bias[t] = 0.5f * bsum;
    }
}

// ---------------- count degrees: 4 edges/thread via int4 ----------------
__global__ void count_deg_kernel(const int* __restrict__ ei) {
    int t = blockIdx.x * blockDim.x + threadIdx.x;
    if (t < NEDGES / 4) {
        int4 r = __ldg((const int4*)ei + t);
        int4 c = __ldg((const int4*)(ei + NEDGES) + t);
        atomicAdd(&g_deg_out[r.x], 1);
        atomicAdd(&g_deg_out[r.y], 1);
        atomicAdd(&g_deg_out[r.z], 1);
        atomicAdd(&g_deg_out[r.w], 1);
        atomicAdd(&g_deg_in[c.x], 1);
        atomicAdd(&g_deg_in[c.y], 1);
        atomicAdd(&g_deg_in[c.z], 1);
        atomicAdd(&g_deg_in[c.w], 1);
    }
}

// ---------------- single-pass exclusive scan (decoupled lookback) ----------------
__global__ void scan_lookback_kernel() {
    __shared__ int s[1024];
    __shared__ int s_prefix;
    const int sel = blockIdx.y;
    const int* deg = sel ? g_deg_in : g_deg_out;
    unsigned long long* tstat = g_tstat[sel];
    int* rowptr = sel ? g_rowptrAT : g_rowptrA;
    int* cursor = sel ? g_curAT : g_curA;
    float* nrm  = sel ? g_i : g_o;

    const int tid = threadIdx.x;
    const int i = blockIdx.x * 1024 + tid;
    int v = (i < NNODES) ? deg[i] : 0;
    s[tid] = v;
    __syncthreads();
    #pragma unroll
    for (int off = 1; off < 1024; off <<= 1) {
        int t = (tid >= off) ? s[tid - off] : 0;
        __syncthreads();
        s[tid] += t;
        __syncthreads();
    }
    int incl = s[tid];
    int aggregate = s[1023];

    if (tid == 0) {
        if (blockIdx.x == 0) {
            atomicExch(&tstat[0], (2ull << 32) | (unsigned)aggregate);
            s_prefix = 0;
        } else {
            atomicExch(&tstat[blockIdx.x], (1ull << 32) | (unsigned)aggregate);
            int pfx = 0;
            int j = blockIdx.x - 1;
            for (;;) {
                unsigned long long st;
                do { st = atomicAdd(&tstat[j], 0ull); } while ((st >> 32) == 0ull);
                pfx += (int)(unsigned)st;
                if ((st >> 32) == 2ull) break;
                j--;
            }
            atomicExch(&tstat[blockIdx.x], (2ull << 32) | (unsigned)(aggregate + pfx));
            s_prefix = pfx;
        }
    }
    __syncthreads();

    if (i < NNODES) {
        int excl = s_prefix + incl - v;
        rowptr[i] = excl;
        cursor[i] = excl;
        nrm[i] = (v > 0) ? rsqrtf((float)v) : 0.0f;
    }
    if (i == 0) rowptr[NNODES] = NEDGES;
}

// ---------------- merged combine + fill_csr (both depend only on scan) ----------------
__global__ void combfill_kernel(const float* __restrict__ x, const int* __restrict__ ei) {
    int t = blockIdx.x * blockDim.x + threadIdx.x;

    // fill CSR: 4 edges/thread, independent atomic chains
    if (t < NEDGES / 4) {
        int4 r = __ldg((const int4*)ei + t);
        int4 c = __ldg((const int4*)(ei + NEDGES) + t);
        int p0 = atomicAdd(&g_curA[r.x], 1);
        int p1 = atomicAdd(&g_curA[r.y], 1);
        int p2 = atomicAdd(&g_curA[r.z], 1);
        int p3 = atomicAdd(&g_curA[r.w], 1);
        int q0 = atomicAdd(&g_curAT[c.x], 1);
        int q1 = atomicAdd(&g_curAT[c.y], 1);
        int q2 = atomicAdd(&g_curAT[c.z], 1);
        int q3 = atomicAdd(&g_curAT[c.w], 1);
        g_colA[p0] = c.x;
        g_colA[p1] = c.y;
        g_colA[p2] = c.z;
        g_colA[p3] = c.w;
        g_colAT[q0] = r.x;
        g_colAT[q1] = r.y;
        g_colAT[q2] = r.z;
        g_colAT[q3] = r.w;
    }

    // combine: x -> i~*x (fp16) + derived row scales
    if (t < NNODES * 16) {
        int r = t >> 4;
        float ii = g_i[r];
        float it = (ii > 0.f) ? ii : 1.0f;
        float4 v = __ldg((const float4*)x + t);
        __half2 h0 = __floats2half2_rn(it * v.x, it * v.y);
        __half2 h1 = __floats2half2_rn(it * v.z, it * v.w);
        uint2 o;
        o.x = *reinterpret_cast<unsigned*>(&h0);
        o.y = *reinterpret_cast<unsigned*>(&h1);
        *((uint2*)g_xh + t) = o;
    }
    if (t < NNODES) {
        float ii = g_i[t];
        float oo = g_o[t];
        float it = (ii > 0.f) ? ii : 1.0f;
        float ot = (oo > 0.f) ? oo : 1.0f;
        g_schain[t] = it * oo;
        g_gs[t] = make_float2(1.0f / it, ot / it);
    }
}

// ---------------- SpMM: plain gather + per-row scale (proven unroll-2 body) ----------------
__global__ void spmm_kernel(const int* __restrict__ rowptr, const int* __restrict__ cidx,
                            const float* __restrict__ ss, const __half* __restrict__ h,
                            __half* __restrict__ yout, float* __restrict__ outf,
                            const float* __restrict__ bias, int mode) {
    int gt = blockIdx.x * blockDim.x + threadIdx.x;
    int r = gt >> 3;
    if (r >= NNODES) return;
    int lane = gt & 7;

    int k = __ldg(rowptr + r);
    int end = __ldg(rowptr + r + 1);
    float a[8] = {0.f, 0.f, 0.f, 0.f, 0.f, 0.f, 0.f, 0.f};
    float b[8] = {0.f, 0.f, 0.f, 0.f, 0.f, 0.f, 0.f, 0.f};

    const __half* hl = h + (lane << 3);
    while (k + 2 <= end) {
        int c0 = __ldg(cidx + k);
        int c1 = __ldg(cidx + k + 1);
        uint4 h0 = __ldg((const uint4*)(hl + ((size_t)c0 << 6)));
        uint4 h1 = __ldg((const uint4*)(hl + ((size_t)c1 << 6)));
        const unsigned* p0 = &h0.x;
        const unsigned* p1 = &h1.x;
        #pragma unroll
        for (int q = 0; q < 4; q++) {
            float2 f0 = __half22float2(*reinterpret_cast<const __half2*>(p0 + q));
            float2 f1 = __half22float2(*reinterpret_cast<const __half2*>(p1 + q));
            a[q * 2]     += f0.x;
            a[q * 2 + 1] += f0.y;
            b[q * 2]     += f1.x;
            b[q * 2 + 1] += f1.y;
        }
        k += 2;
    }
    if (k < end) {
        int c0 = __ldg(cidx + k);
        uint4 h0 = __ldg((const uint4*)(hl + ((size_t)c0 << 6)));
        const unsigned* p0 = &h0.x;
        #pragma unroll
        for (int q = 0; q < 4; q++) {
            float2 f0 = __half22float2(*reinterpret_cast<const __half2*>(p0 + q));
            a[q * 2]     += f0.x;
            a[q * 2 + 1] += f0.y;
        }
    }
    #pragma unroll
    for (int q = 0; q < 8; q++) a[q] += b[q];

    float s = ss[r];
    if (mode == 0) {
        uint4 o;
        __half2 h0 = __floats2half2_rn(s * a[0], s * a[1]);
        __half2 h1 = __floats2half2_rn(s * a[2], s * a[3]);
        __half2 h2 = __floats2half2_rn(s * a[4], s * a[5]);
        __half2 h3 = __floats2half2_rn(s * a[6], s * a[7]);
        o.x = *reinterpret_cast<unsigned*>(&h0);
        o.y = *reinterpret_cast<unsigned*>(&h1);
        o.z = *reinterpret_cast<unsigned*>(&h2);
        o.w = *reinterpret_cast<unsigned*>(&h3);
        *(uint4*)(yout + ((size_t)r << 6) + (lane << 3)) = o;
    } else {
        size_t off = ((size_t)r << 6) + (lane << 3);
        float4 p0 = *reinterpret_cast<float4*>(outf + off);
        float4 p1 = *reinterpret_cast<float4*>(outf + off + 4);
        float4 bv0 = *reinterpret_cast<const float4*>(bias + (lane << 3));
        float4 bv1 = *reinterpret_cast<const float4*>(bias + (lane << 3) + 4);
        float4 r0, r1;
        r0.x = p0.x + bv0.x + s * a[0];
        r0.y = p0.y + bv0.y + s * a[1];
        r0.z = p0.z + bv0.z + s * a[2];
        r0.w = p0.w + bv0.w + s * a[3];
        r1.x = p1.x + bv1.x + s * a[4];
        r1.y = p1.y + bv1.y + s * a[5];
        r1.z = p1.z + bv1.z + s * a[6];
        r1.w = p1.w + bv1.w + s * a[7];
        *reinterpret_cast<float4*>(outf + off)     = r0;
        *reinterpret_cast<float4*>(outf + off + 4) = r1;
    }
}

// ---------------- Mega-GEMM via HMMA with per-row epilogue scales ----------------
#define LDS_K 40
__global__ __launch_bounds__(256) void mega_gemm_kernel(
    float* __restrict__ out, __half* __restrict__ Zh)
{
    __shared__ __half sA[128 * LDS_K];
    __shared__ __half sB[128 * LDS_K];
    __shared__ float patch[8][16 * 16];

    const int tid  = threadIdx.x;
    const int wid  = tid >> 5;
    const int row0 = blockIdx.x * 128;
    const int wr   = wid & 3;
    const int wc   = wid >> 2;

    wmma::fragment<wmma::accumulator, 16, 16, 16, float> acc[2][4];
    #pragma unroll
    for (int i = 0; i < 2; i++)
        #pragma unroll
        for (int j = 0; j < 4; j++) wmma::fill_fragment(acc[i][j], 0.0f);

    const __half* srcs[5] = {g_xh, g_y1h, g_y2h, g_y3h, g_y4h};

    const int srow  = tid >> 1;
    const int spart = (tid & 1) * 16;

    #pragma unroll
    for (int g = 0; g < 10; g++) {
        const __half* src = srcs[g >> 1];
        const int kbase = (g & 1) * 32;

        __syncthreads();
        {
            int grow = row0 + srow;
            uint4 v0 = make_uint4(0, 0, 0, 0), v1 = v0;
            if (grow < NNODES) {
                const uint4* p = (const uint4*)(src + (size_t)grow * 64 + kbase + spart);
                v0 = __ldg(p);
                v1 = __ldg(p + 1);
            }
            *(uint4*)&sA[srow * LDS_K + spart]     = v0;
            *(uint4*)&sA[srow * LDS_K + spart + 8] = v1;
        }
        {
            const uint4* p = (const uint4*)(g_Uh + (size_t)srow * 320 + (g >> 1) * 64 + kbase + spart);
            uint4 v0 = __ldg(p);
            uint4 v1 = __ldg(p + 1);
            *(uint4*)&sB[srow * LDS_K + spart]     = v0;
            *(uint4*)&sB[srow * LDS_K + spart + 8] = v1;
        }
        __syncthreads();

        #pragma unroll
        for (int ks = 0; ks < 32; ks += 16) {
            wmma::fragment<wmma::matrix_a, 16, 16, 16, __half, wmma::row_major> af[2];
            wmma::load_matrix_sync(af[0], &sA[(wr * 32 +  0) * LDS_K + ks], LDS_K);
            wmma::load_matrix_sync(af[1], &sA[(wr * 32 + 16) * LDS_K + ks], LDS_K);
            #pragma unroll
            for (int j = 0; j < 4; j++) {
                wmma::fragment<wmma::matrix_b, 16, 16, 16, __half, wmma::col_major> bf;
                wmma::load_matrix_sync(bf, &sB[(wc * 64 + j * 16) * LDS_K + ks], LDS_K);
                wmma::mma_sync(acc[0][j], af[0], bf, acc[0][j]);
                wmma::mma_sync(acc[1][j], af[1], bf, acc[1][j]);
            }
        }
    }

    const int lane = tid & 31;
    #pragma unroll
    for (int i = 0; i < 2; i++) {
        int rbase = row0 + wr * 32 + i * 16;
        if (rbase >= NNODES) continue;
        #pragma unroll
        for (int j = 0; j < 4; j++) {
            wmma::store_matrix_sync(patch[wid], acc[i][j], 16, wmma::mem_row_major);
            __syncwarp();
            int pr = lane >> 1;
            int pc = (lane & 1) * 8;
            int r = rbase + pr;
            const float* pp = &patch[wid][pr * 16 + pc];
            float2 gsr = g_gs[r];
            if (wc == 0) {
                float s = gsr.x;
                float4 o0 = make_float4(pp[0] * s, pp[1] * s, pp[2] * s, pp[3] * s);
                float4 o1 = make_float4(pp[4] * s, pp[5] * s, pp[6] * s, pp[7] * s);
                float* dst = out + (size_t)r * 64 + j * 16 + pc;
                *reinterpret_cast<float4*>(dst)     = o0;
                *reinterpret_cast<float4*>(dst + 4) = o1;
            } else {
                float s = gsr.y;
                __half2 h0 = __floats2half2_rn(pp[0] * s, pp[1] * s);
                __half2 h1 = __floats2half2_rn(pp[2] * s, pp[3] * s);
                __half2 h2 = __floats2half2_rn(pp[4] * s, pp[5] * s);
                __half2 h3 = __floats2half2_rn(pp[6] * s, pp[7] * s);
                uint4 o;
                o.x = *reinterpret_cast<unsigned*>(&h0);
                o.y = *reinterpret_cast<unsigned*>(&h1);
                o.z = *reinterpret_cast<unsigned*>(&h2);
                o.w = *reinterpret_cast<unsigned*>(&h3);
                *(uint4*)(Zh + (size_t)r * 64 + j * 16 + pc) = o;
            }
            __syncwarp();
        }
    }
}

// ---------------- launch ----------------
extern "C" void kernel_launch(void* const* d_in, const int* in_sizes, int n_in,
                              void* d_out, int out_size) {
    const float* x    = (const float*)d_in[0];
    const int*   ei   = (const int*)d_in[1];
    const float* Wsd  = (const float*)d_in[2];
    const float* bssd = (const float*)d_in[3];
    const float* Wds  = (const float*)d_in[4];
    const float* bsds = (const float*)d_in[5];
    const float* W0sd = (const float*)d_in[6];
    const float* b0sd = (const float*)d_in[7];
    const float* W0ds = (const float*)d_in[8];
    const float* b0ds = (const float*)d_in[9];
    float* out = (float*)d_out;

    void* tmp;
    cudaGetSymbolAddress(&tmp, g_xh);       __half* xh  = (__half*)tmp;
    cudaGetSymbolAddress(&tmp, g_y1h);      __half* y1h = (__half*)tmp;
    cudaGetSymbolAddress(&tmp, g_y2h);      __half* y2h = (__half*)tmp;
    cudaGetSymbolAddress(&tmp, g_y3h);      __half* y3h = (__half*)tmp;
    cudaGetSymbolAddress(&tmp, g_y4h);      __half* y4h = (__half*)tmp;
    cudaGetSymbolAddress(&tmp, g_Zh);       __half* Zh  = (__half*)tmp;
    cudaGetSymbolAddress(&tmp, g_bias);     float* bias = (float*)tmp;
    cudaGetSymbolAddress(&tmp, g_rowptrA);  int* rpA  = (int*)tmp;
    cudaGetSymbolAddress(&tmp, g_rowptrAT); int* rpAT = (int*)tmp;
    cudaGetSymbolAddress(&tmp, g_colA);     int* cA   = (int*)tmp;
    cudaGetSymbolAddress(&tmp, g_colAT);    int* cAT  = (int*)tmp;
    cudaGetSymbolAddress(&tmp, g_schain);   float* schain = (float*)tmp;
    cudaGetSymbolAddress(&tmp, g_i);        float* ni = (float*)tmp;

    const int nblk_nodes = (NNODES + 255) / 256;         // 391
    const int nblk_edge4 = (NEDGES / 4 + 255) / 256;     // 1563
    const int nblk_comb  = (NNODES * 16 + 255) / 256;    // 6250 (covers fill too)
    const int nblk_spmm  = (NNODES * 8 + 255) / 256;     // 3125
    const int nblk_gemm  = (NNODES + 127) / 128;         // 782

    // ---- preprocessing (4 launches) ----
    init_kernel<<<nblk_nodes, 256>>>(Wsd, Wds, W0sd, W0ds, bssd, bsds, b0sd, b0ds);
    count_deg_kernel<<<nblk_edge4, 256>>>(ei);
    scan_lookback_kernel<<<dim3(NSCANBLK, 2), 1024>>>();
    combfill_kernel<<<nblk_comb, 256>>>(x, ei);

    // ---- hop chain (4 separate launches — measured faster than persistent) ----
    spmm_kernel<<<nblk_spmm, 256>>>(rpA, cA, schain, xh,  y1h, nullptr, nullptr, 0);
    spmm_kernel<<<nblk_spmm, 256>>>(rpA, cA, schain, y1h, y2h, nullptr, nullptr, 0);
    spmm_kernel<<<nblk_spmm, 256>>>(rpA, cA, schain, y2h, y3h, nullptr, nullptr, 0);
    spmm_kernel<<<nblk_spmm, 256>>>(rpA, cA, schain, y3h, y4h, nullptr, nullptr, 0);

    // ---- fused HMMA GEMM ----
    mega_gemm_kernel<<<nblk_gemm, 256>>>(out, Zh);

    // ---- out += bias + i[r] * gather(Zhat) ----
    spmm_kernel<<<nblk_spmm, 256>>>(rpAT, cAT, ni, Zh, nullptr, out, bias, 1);
}

// round 11
// speedup vs baseline: 1.1116x; 1.0101x over previous
#include <cuda_runtime.h>
#include <cuda_fp16.h>
#include <mma.h>
#include <cstdint>

using namespace nvcuda;

#define NNODES 100000
#define NEDGES 1600000
#define NSCANBLK 98        // ceil(NNODES/1024)

// ---------------- device scratch ----------------
__device__ int    g_deg_out[NNODES];
__device__ int    g_deg_in[NNODES];
__device__ float  g_o[NNODES];
__device__ float  g_i[NNODES];
__device__ float  g_schain[NNODES];     // i~[r]*o[r]
__device__ float2 g_gs[NNODES];         // {1/i~[r], o~[r]/i~[r]}
__device__ int    g_rowptrA[NNODES + 1];
__device__ int    g_rowptrAT[NNODES + 1];
__device__ int    g_loA[NEDGES];        // per-edge local offset within row (A side)
__device__ int    g_loAT[NEDGES];       // per-edge local offset within col (AT side)
__device__ int    g_colA[NEDGES];
__device__ int    g_colAT[NEDGES];
__device__ unsigned long long g_tstat[2][NSCANBLK];
__device__ __half g_xh [(size_t)NNODES * 64];
__device__ __half g_y1h[(size_t)NNODES * 64];
__device__ __half g_y2h[(size_t)NNODES * 64];
__device__ __half g_y3h[(size_t)NNODES * 64];
__device__ __half g_y4h[(size_t)NNODES * 64];
__device__ __half g_Zh [(size_t)NNODES * 64];
__device__ float  g_bias[64];
__device__ __half g_Uh[128 * 320];

// ---------------- init: zero degs/status + build U/bias ----------------
__global__ void init_kernel(const float* __restrict__ Wsd, const float* __restrict__ Wds,
                            const float* __restrict__ W0sd, const float* __restrict__ W0ds,
                            const float* __restrict__ bssd, const float* __restrict__ bsds,
                            const float* __restrict__ b0sd, const float* __restrict__ b0ds) {
    int t = blockIdx.x * blockDim.x + threadIdx.x;
    if (t < NNODES) { g_deg_out[t] = 0; g_deg_in[t] = 0; }
    if (t < 2 * NSCANBLK) g_tstat[t >= NSCANBLK][t % NSCANBLK] = 0ull;

    if (t < 128 * 320) {
        int c = t / 320;
        int kk = t - c * 320;
        int b = kk >> 6;
        int k = kk & 63;
        float v;
        float coef = exp2f(-(float)b);
        if (c < 64) {
            if (b == 0) v = 0.5f * (W0sd[c * 64 + k] + W0ds[c * 64 + k]);
            else        v = coef * Wsd[(b - 1) * 4096 + c * 64 + k];
        } else {
            int cc = c - 64;
            if (b == 0)      v = 0.5f * Wds[cc * 64 + k];
            else if (b == 1) v = 0.0f;
            else             v = coef * Wds[(b - 1) * 4096 + cc * 64 + k];
        }
        g_Uh[t] = __float2half(v);
    }
    if (t < 64) {
        float bsum = b0sd[t] + b0ds[t];
        float sc = 1.0f;
        #pragma unroll
        for (int kk = 0; kk < 4; kk++) {
            bsum += sc * (bssd[kk * 64 + t] + bsds[kk * 64 + t]);
            sc *= 0.5f;
        }
        g_bias[t] = 0.5f * bsum;
    }
}

// ---------------- pass 1: count degrees AND save per-edge local offsets ----------------
__global__ void count_loc_kernel(const int* __restrict__ ei) {
    int t = blockIdx.x * blockDim.x + threadIdx.x;
    if (t < NEDGES / 4) {
        int4 r = __ldg((const int4*)ei + t);
        int4 c = __ldg((const int4*)(ei + NEDGES) + t);
        int4 lr, lc;
        lr.x = atomicAdd(&g_deg_out[r.x], 1);
        lr.y = atomicAdd(&g_deg_out[r.y], 1);
        lr.z = atomicAdd(&g_deg_out[r.z], 1);
        lr.w = atomicAdd(&g_deg_out[r.w], 1);
        lc.x = atomicAdd(&g_deg_in[c.x], 1);
        lc.y = atomicAdd(&g_deg_in[c.y], 1);
        lc.z = atomicAdd(&g_deg_in[c.z], 1);
        lc.w = atomicAdd(&g_deg_in[c.w], 1);
        ((int4*)g_loA)[t]  = lr;   // coalesced
        ((int4*)g_loAT)[t] = lc;
    }
}

// ---------------- single-pass exclusive scan (decoupled lookback) ----------------
__global__ void scan_lookback_kernel() {
    __shared__ int s[1024];
    __shared__ int s_prefix;
    const int sel = blockIdx.y;
    const int* deg = sel ? g_deg_in : g_deg_out;
    unsigned long long* tstat = g_tstat[sel];
    int* rowptr = sel ? g_rowptrAT : g_rowptrA;
    float* nrm  = sel ? g_i : g_o;

    const int tid = threadIdx.x;
    const int i = blockIdx.x * 1024 + tid;
    int v = (i < NNODES) ? deg[i] : 0;
    s[tid] = v;
    __syncthreads();
    #pragma unroll
    for (int off = 1; off < 1024; off <<= 1) {
        int t = (tid >= off) ? s[tid - off] : 0;
        __syncthreads();
        s[tid] += t;
        __syncthreads();
    }
    int incl = s[tid];
    int aggregate = s[1023];

    if (tid == 0) {
        if (blockIdx.x == 0) {
            atomicExch(&tstat[0], (2ull << 32) | (unsigned)aggregate);
            s_prefix = 0;
        } else {
            atomicExch(&tstat[blockIdx.x], (1ull << 32) | (unsigned)aggregate);
            int pfx = 0;
            int j = blockIdx.x - 1;
            for (;;) {
                unsigned long long st;
                do { st = atomicAdd(&tstat[j], 0ull); } while ((st >> 32) == 0ull);
                pfx += (int)(unsigned)st;
                if ((st >> 32) == 2ull) break;
                j--;
            }
            atomicExch(&tstat[blockIdx.x], (2ull << 32) | (unsigned)(aggregate + pfx));
            s_prefix = pfx;
        }
    }
    __syncthreads();

    if (i < NNODES) {
        int excl = s_prefix + incl - v;
        rowptr[i] = excl;
        nrm[i] = (v > 0) ? rsqrtf((float)v) : 0.0f;
    }
    if (i == 0) rowptr[NNODES] = NEDGES;
}

// ---------------- pass 2: atomic-free CSR fill + combine (merged) ----------------
__global__ void combfill_kernel(const float* __restrict__ x, const int* __restrict__ ei) {
    int t = blockIdx.x * blockDim.x + threadIdx.x;

    // fill CSR: position = rowptr[r] + saved local offset; NO atomics, all independent.
    if (t < NEDGES / 4) {
        int4 r  = __ldg((const int4*)ei + t);
        int4 c  = __ldg((const int4*)(ei + NEDGES) + t);
        int4 lr = ((const int4*)g_loA)[t];
        int4 lc = ((const int4*)g_loAT)[t];
        int p0 = __ldg(g_rowptrA + r.x) + lr.x;
        int p1 = __ldg(g_rowptrA + r.y) + lr.y;
        int p2 = __ldg(g_rowptrA + r.z) + lr.z;
        int p3 = __ldg(g_rowptrA + r.w) + lr.w;
        int q0 = __ldg(g_rowptrAT + c.x) + lc.x;
        int q1 = __ldg(g_rowptrAT + c.y) + lc.y;
        int q2 = __ldg(g_rowptrAT + c.z) + lc.z;
        int q3 = __ldg(g_rowptrAT + c.w) + lc.w;
        g_colA[p0] = c.x;
        g_colA[p1] = c.y;
        g_colA[p2] = c.z;
        g_colA[p3] = c.w;
        g_colAT[q0] = r.x;
        g_colAT[q1] = r.y;
        g_colAT[q2] = r.z;
        g_colAT[q3] = r.w;
    }

    // combine: x -> i~*x (fp16) + derived row scales
    if (t < NNODES * 16) {
        int r = t >> 4;
        float ii = g_i[r];
        float it = (ii > 0.f) ? ii : 1.0f;
        float4 v = __ldg((const float4*)x + t);
        __half2 h0 = __floats2half2_rn(it * v.x, it * v.y);
        __half2 h1 = __floats2half2_rn(it * v.z, it * v.w);
        uint2 o;
        o.x = *reinterpret_cast<unsigned*>(&h0);
        o.y = *reinterpret_cast<unsigned*>(&h1);
        *((uint2*)g_xh + t) = o;
    }
    if (t < NNODES) {
        float ii = g_i[t];
        float oo = g_o[t];
        float it = (ii > 0.f) ? ii : 1.0f;
        float ot = (oo > 0.f) ? oo : 1.0f;
        g_schain[t] = it * oo;
        g_gs[t] = make_float2(1.0f / it, ot / it);
    }
}

// ---------------- SpMM: plain gather + per-row scale (proven unroll-2 body) ----------------
__global__ void spmm_kernel(const int* __restrict__ rowptr, const int* __restrict__ cidx,
                            const float* __restrict__ ss, const __half* __restrict__ h,
                            __half* __restrict__ yout, float* __restrict__ outf,
                            const float* __restrict__ bias, int mode) {
    int gt = blockIdx.x * blockDim.x + threadIdx.x;
    int r = gt >> 3;
    if (r >= NNODES) return;
    int lane = gt & 7;

    int k = __ldg(rowptr + r);
    int end = __ldg(rowptr + r + 1);
    float a[8] = {0.f, 0.f, 0.f, 0.f, 0.f, 0.f, 0.f, 0.f};
    float b[8] = {0.f, 0.f, 0.f, 0.f, 0.f, 0.f, 0.f, 0.f};

    const __half* hl = h + (lane << 3);
    while (k + 2 <= end) {
        int c0 = __ldg(cidx + k);
        int c1 = __ldg(cidx + k + 1);
        uint4 h0 = __ldg((const uint4*)(hl + ((size_t)c0 << 6)));
        uint4 h1 = __ldg((const uint4*)(hl + ((size_t)c1 << 6)));
        const unsigned* p0 = &h0.x;
        const unsigned* p1 = &h1.x;
        #pragma unroll
        for (int q = 0; q < 4; q++) {
            float2 f0 = __half22float2(*reinterpret_cast<const __half2*>(p0 + q));
            float2 f1 = __half22float2(*reinterpret_cast<const __half2*>(p1 + q));
            a[q * 2]     += f0.x;
            a[q * 2 + 1] += f0.y;
            b[q * 2]     += f1.x;
            b[q * 2 + 1] += f1.y;
        }
        k += 2;
    }
    if (k < end) {
        int c0 = __ldg(cidx + k);
        uint4 h0 = __ldg((const uint4*)(hl + ((size_t)c0 << 6)));
        const unsigned* p0 = &h0.x;
        #pragma unroll
        for (int q = 0; q < 4; q++) {
            float2 f0 = __half22float2(*reinterpret_cast<const __half2*>(p0 + q));
            a[q * 2]     += f0.x;
            a[q * 2 + 1] += f0.y;
        }
    }
    #pragma unroll
    for (int q = 0; q < 8; q++) a[q] += b[q];

    float s = ss[r];
    if (mode == 0) {
        uint4 o;
        __half2 h0 = __floats2half2_rn(s * a[0], s * a[1]);
        __half2 h1 = __floats2half2_rn(s * a[2], s * a[3]);
        __half2 h2 = __floats2half2_rn(s * a[4], s * a[5]);
        __half2 h3 = __floats2half2_rn(s * a[6], s * a[7]);
        o.x = *reinterpret_cast<unsigned*>(&h0);
        o.y = *reinterpret_cast<unsigned*>(&h1);
        o.z = *reinterpret_cast<unsigned*>(&h2);
        o.w = *reinterpret_cast<unsigned*>(&h3);
        *(uint4*)(yout + ((size_t)r << 6) + (lane << 3)) = o;
    } else {
        size_t off = ((size_t)r << 6) + (lane << 3);
        float4 p0 = *reinterpret_cast<float4*>(outf + off);
        float4 p1 = *reinterpret_cast<float4*>(outf + off + 4);
        float4 bv0 = *reinterpret_cast<const float4*>(bias + (lane << 3));
        float4 bv1 = *reinterpret_cast<const float4*>(bias + (lane << 3) + 4);
        float4 r0, r1;
        r0.x = p0.x + bv0.x + s * a[0];
        r0.y = p0.y + bv0.y + s * a[1];
        r0.z = p0.z + bv0.z + s * a[2];
        r0.w = p0.w + bv0.w + s * a[3];
        r1.x = p1.x + bv1.x + s * a[4];
        r1.y = p1.y + bv1.y + s * a[5];
        r1.z = p1.z + bv1.z + s * a[6];
        r1.w = p1.w + bv1.w + s * a[7];
        *reinterpret_cast<float4*>(outf + off)     = r0;
        *reinterpret_cast<float4*>(outf + off + 4) = r1;
    }
}

// ---------------- Mega-GEMM via HMMA with per-row epilogue scales ----------------
#define LDS_K 40
__global__ __launch_bounds__(256) void mega_gemm_kernel(
    float* __restrict__ out, __half* __restrict__ Zh)
{
    __shared__ __half sA[128 * LDS_K];
    __shared__ __half sB[128 * LDS_K];
    __shared__ float patch[8][16 * 16];

    const int tid  = threadIdx.x;
    const int wid  = tid >> 5;
    const int row0 = blockIdx.x * 128;
    const int wr   = wid & 3;
    const int wc   = wid >> 2;

    wmma::fragment<wmma::accumulator, 16, 16, 16, float> acc[2][4];
    #pragma unroll
    for (int i = 0; i < 2; i++)
        #pragma unroll
        for (int j = 0; j < 4; j++) wmma::fill_fragment(acc[i][j], 0.0f);

    const __half* srcs[5] = {g_xh, g_y1h, g_y2h, g_y3h, g_y4h};

    const int srow  = tid >> 1;
    const int spart = (tid & 1) * 16;

    #pragma unroll
    for (int g = 0; g < 10; g++) {
        const __half* src = srcs[g >> 1];
        const int kbase = (g & 1) * 32;

        __syncthreads();
        {
            int grow = row0 + srow;
            uint4 v0 = make_uint4(0, 0, 0, 0), v1 = v0;
            if (grow < NNODES) {
                const uint4* p = (const uint4*)(src + (size_t)grow * 64 + kbase + spart);
                v0 = __ldg(p);
                v1 = __ldg(p + 1);
            }
            *(uint4*)&sA[srow * LDS_K + spart]     = v0;
            *(uint4*)&sA[srow * LDS_K + spart + 8] = v1;
        }
        {
            const uint4* p = (const uint4*)(g_Uh + (size_t)srow * 320 + (g >> 1) * 64 + kbase + spart);
            uint4 v0 = __ldg(p);
            uint4 v1 = __ldg(p + 1);
            *(uint4*)&sB[srow * LDS_K + spart]     = v0;
            *(uint4*)&sB[srow * LDS_K + spart + 8] = v1;
        }
        __syncthreads();

        #pragma unroll
        for (int ks = 0; ks < 32; ks += 16) {
            wmma::fragment<wmma::matrix_a, 16, 16, 16, __half, wmma::row_major> af[2];
            wmma::load_matrix_sync(af[0], &sA[(wr * 32 +  0) * LDS_K + ks], LDS_K);
            wmma::load_matrix_sync(af[1], &sA[(wr * 32 + 16) * LDS_K + ks], LDS_K);
            #pragma unroll
            for (int j = 0; j < 4; j++) {
                wmma::fragment<wmma::matrix_b, 16, 16, 16, __half, wmma::col_major> bf;
                wmma::load_matrix_sync(bf, &sB[(wc * 64 + j * 16) * LDS_K + ks], LDS_K);
                wmma::mma_sync(acc[0][j], af[0], bf, acc[0][j]);
                wmma::mma_sync(acc[1][j], af[1], bf, acc[1][j]);
            }
        }
    }

    const int lane = tid & 31;
    #pragma unroll
    for (int i = 0; i < 2; i++) {
        int rbase = row0 + wr * 32 + i * 16;
        if (rbase >= NNODES) continue;
        #pragma unroll
        for (int j = 0; j < 4; j++) {
            wmma::store_matrix_sync(patch[wid], acc[i][j], 16, wmma::mem_row_major);
            __syncwarp();
            int pr = lane >> 1;
            int pc = (lane & 1) * 8;
            int r = rbase + pr;
            const float* pp = &patch[wid][pr * 16 + pc];
            float2 gsr = g_gs[r];
            if (wc == 0) {
                float s = gsr.x;
                float4 o0 = make_float4(pp[0] * s, pp[1] * s, pp[2] * s, pp[3] * s);
                float4 o1 = make_float4(pp[4] * s, pp[5] * s, pp[6] * s, pp[7] * s);
                float* dst = out + (size_t)r * 64 + j * 16 + pc;
                *reinterpret_cast<float4*>(dst)     = o0;
                *reinterpret_cast<float4*>(dst + 4) = o1;
            } else {
                float s = gsr.y;
                __half2 h0 = __floats2half2_rn(pp[0] * s, pp[1] * s);
                __half2 h1 = __floats2half2_rn(pp[2] * s, pp[3] * s);
                __half2 h2 = __floats2half2_rn(pp[4] * s, pp[5] * s);
                __half2 h3 = __floats2half2_rn(pp[6] * s, pp[7] * s);
                uint4 o;
                o.x = *reinterpret_cast<unsigned*>(&h0);
                o.y = *reinterpret_cast<unsigned*>(&h1);
                o.z = *reinterpret_cast<unsigned*>(&h2);
                o.w = *reinterpret_cast<unsigned*>(&h3);
                *(uint4*)(Zh + (size_t)r * 64 + j * 16 + pc) = o;
            }
            __syncwarp();
        }
    }
}

// ---------------- launch ----------------
extern "C" void kernel_launch(void* const* d_in, const int* in_sizes, int n_in,
                              void* d_out, int out_size) {
    const float* x    = (const float*)d_in[0];
    const int*   ei   = (const int*)d_in[1];
    const float* Wsd  = (const float*)d_in[2];
    const float* bssd = (const float*)d_in[3];
    const float* Wds  = (const float*)d_in[4];
    const float* bsds = (const float*)d_in[5];
    const float* W0sd = (const float*)d_in[6];
    const float* b0sd = (const float*)d_in[7];
    const float* W0ds = (const float*)d_in[8];
    const float* b0ds = (const float*)d_in[9];
    float* out = (float*)d_out;

    void* tmp;
    cudaGetSymbolAddress(&tmp, g_xh);       __half* xh  = (__half*)tmp;
    cudaGetSymbolAddress(&tmp, g_y1h);      __half* y1h = (__half*)tmp;
    cudaGetSymbolAddress(&tmp, g_y2h);      __half* y2h = (__half*)tmp;
    cudaGetSymbolAddress(&tmp, g_y3h);      __half* y3h = (__half*)tmp;
    cudaGetSymbolAddress(&tmp, g_y4h);      __half* y4h = (__half*)tmp;
    cudaGetSymbolAddress(&tmp, g_Zh);       __half* Zh  = (__half*)tmp;
    cudaGetSymbolAddress(&tmp, g_bias);     float* bias = (float*)tmp;
    cudaGetSymbolAddress(&tmp, g_rowptrA);  int* rpA  = (int*)tmp;
    cudaGetSymbolAddress(&tmp, g_rowptrAT); int* rpAT = (int*)tmp;
    cudaGetSymbolAddress(&tmp, g_colA);     int* cA   = (int*)tmp;
    cudaGetSymbolAddress(&tmp, g_colAT);    int* cAT  = (int*)tmp;
    cudaGetSymbolAddress(&tmp, g_schain);   float* schain = (float*)tmp;
    cudaGetSymbolAddress(&tmp, g_i);        float* ni = (float*)tmp;

    const int nblk_nodes = (NNODES + 255) / 256;         // 391
    const int nblk_edge4 = (NEDGES / 4 + 255) / 256;     // 1563
    const int nblk_comb  = (NNODES * 16 + 255) / 256;    // 6250 (covers fill too)
    const int nblk_spmm  = (NNODES * 8 + 255) / 256;     // 3125
    const int nblk_gemm  = (NNODES + 127) / 128;         // 782

    // ---- preprocessing (4 launches) ----
    init_kernel<<<nblk_nodes, 256>>>(Wsd, Wds, W0sd, W0ds, bssd, bsds, b0sd, b0ds);
    count_loc_kernel<<<nblk_edge4, 256>>>(ei);
    scan_lookback_kernel<<<dim3(NSCANBLK, 2), 1024>>>();
    combfill_kernel<<<nblk_comb, 256>>>(x, ei);

    // ---- hop chain (4 separate launches) ----
    spmm_kernel<<<nblk_spmm, 256>>>(rpA, cA, schain, xh,  y1h, nullptr, nullptr, 0);
    spmm_kernel<<<nblk_spmm, 256>>>(rpA, cA, schain, y1h, y2h, nullptr, nullptr, 0);
    spmm_kernel<<<nblk_spmm, 256>>>(rpA, cA, schain, y2h, y3h, nullptr, nullptr, 0);
    spmm_kernel<<<nblk_spmm, 256>>>(rpA, cA, schain, y3h, y4h, nullptr, nullptr, 0);

    // ---- fused HMMA GEMM ----
    mega_gemm_kernel<<<nblk_gemm, 256>>>(out, Zh);

    // ---- out += bias + i[r] * gather(Zhat) ----
    spmm_kernel<<<nblk_spmm, 256>>>(rpAT, cAT, ni, Zh, nullptr, out, bias, 1);
}